// round 14
// baseline (speedup 1.0000x reference)
#include <cuda_runtime.h>
#include <cstdint>

// ---------------- problem constants ----------------
#define BB   64      // batch
#define TT   512     // seq len
#define EE   256     // embed dim
#define HH   512     // hidden
#define GH   2048    // 4*H
#define CD   4       // classes

// ---------------- scan configuration ----------------
#define NCC    128               // persistent CTAs; CTA cc owns h-cols [4cc, 4cc+4)
#define NROWS  16                // gate rows per CTA = 4 gates x 4 cols
#define KCHUNK 64                // h streaming chunk (k per chunk)
#define NCHUNK 4                 // chunks per k-team (team covers 256 k)
#define WSROW  514               // padded W smem row (floats) = 257 ull (odd)
#define HSROW  68                // padded h smem row (floats) = 34 ull, 272B = 17*16B
#define GAROW  66                // gate-staging row (floats)

// smem float offsets
#define OFF_W   0
#define OFF_H   (NROWS * WSROW)                       // 8224
#define HBUFSZ  (BB * HSROW)                          // 4352 floats per buffer
#define OFF_GA  (OFF_H + 4 * HBUFSZ)                  // 2 teams x 2 bufs
#define SMEM_SCAN ((OFF_GA + 2 * NROWS * GAROW) * 4)  // 110976 B

typedef unsigned long long ull;

#define HSLOT ((size_t)BB * HH)

// ---------------- device scratch (no allocs allowed) ----------------
struct alignas(256) PadFlag { unsigned v; unsigned pad[63]; };

__device__ float   d_xg[(size_t)TT * BB * GH];   // 256 MB: xg[(t*64+b)*2048 + g]
__device__ float   d_hbuf[2 * BB * HH];          // double-buffered h: slot t&1 holds h_t
__device__ PadFlag d_hflag[NCC];                 // v = s: CTA cc has written its h_s cols

// ---------------- helpers ----------------
__device__ __forceinline__ void ffma2(ull& d, ull a, ull b) {
    asm("fma.rn.f32x2 %0, %1, %2, %0;" : "+l"(d) : "l"(a), "l"(b));
}
__device__ __forceinline__ float hadd2(ull u) {
    float lo = __uint_as_float((unsigned)(u & 0xffffffffull));
    float hi = __uint_as_float((unsigned)(u >> 32));
    return lo + hi;
}
__device__ __forceinline__ float tanhfast(float x) {
    float r; asm("tanh.approx.f32 %0, %1;" : "=f"(r) : "f"(x)); return r;
}
__device__ __forceinline__ float sigfast(float x) {
    return fmaf(tanhfast(0.5f * x), 0.5f, 0.5f);
}
__device__ __forceinline__ void st_release(unsigned* p, unsigned v) {
    asm volatile("st.release.gpu.u32 [%0], %1;" :: "l"(p), "r"(v) : "memory");
}
__device__ __forceinline__ unsigned ld_acquire(unsigned* p) {
    unsigned v;
    asm volatile("ld.acquire.gpu.u32 %0, [%1];" : "=r"(v) : "l"(p) : "memory");
    return v;
}
__device__ __forceinline__ void cp_async16(uint32_t saddr, const void* gptr) {
    asm volatile("cp.async.cg.shared.global [%0], [%1], 16;" :: "r"(saddr), "l"(gptr) : "memory");
}
__device__ __forceinline__ void cp_commit() {
    asm volatile("cp.async.commit_group;" ::: "memory");
}
template<int N> __device__ __forceinline__ void cp_wait() {
    asm volatile("cp.async.wait_group %0;" :: "n"(N) : "memory");
}
__device__ __forceinline__ void team_bar(int id) {
    asm volatile("bar.sync %0, 128;" :: "r"(id) : "memory");
}

// ---------------- kernel 0: per-launch reset ----------------
__global__ void init_kernel() {
    int i = blockIdx.x * blockDim.x + threadIdx.x;
    if (i < NCC) d_hflag[i].v = 0u;
    for (int j = i; j < BB * HH; j += gridDim.x * blockDim.x) d_hbuf[j] = 0.0f;  // h_0 (slot 0)
}

// ---------------- kernel 1: fused embedding gather + input GEMM (FFMA2) ---------------
__global__ void __launch_bounds__(256) emb_gemm_kernel(
    const int*   __restrict__ x,
    const float* __restrict__ emb,
    const float* __restrict__ W_ih,
    const float* __restrict__ b_ih,
    const float* __restrict__ b_hh)
{
    __shared__ float As[128 * 20];
    __shared__ float Bs[64 * 18];
    const int tid = threadIdx.x;
    const int m0  = blockIdx.y * 128;
    const int n0  = blockIdx.x * 64;

    const int rA = tid >> 1, kA = (tid & 1) * 8;
    const int tpos = (m0 + rA) >> 6, bpos = rA & 63;
    const float* aptr = emb + (size_t)x[bpos * TT + tpos] * EE + kA;
    const int rB = tid >> 2, kB = (tid & 3) * 4;
    const float* bptr = W_ih + (size_t)(n0 + rB) * EE + kB;

    const int tx = tid & 15, ty = tid >> 4;

    ull acc2[8][4];
#pragma unroll
    for (int i = 0; i < 8; ++i)
#pragma unroll
        for (int c = 0; c < 4; ++c) acc2[i][c] = 0ull;

    const ull* Asu = (const ull*)As;           // row stride 10 ull
    const ull* Bsu = (const ull*)Bs;           // row stride 9 ull

    for (int kt = 0; kt < EE; kt += 16) {
        float4 a0 = *(const float4*)(aptr + kt);
        float4 a1 = *(const float4*)(aptr + kt + 4);
        float4 bv = *(const float4*)(bptr + kt);
        __syncthreads();
        *(float4*)&As[rA * 20 + kA]     = a0;
        *(float4*)&As[rA * 20 + kA + 4] = a1;
        *(float2*)&Bs[rB * 18 + kB]     = make_float2(bv.x, bv.y);
        *(float2*)&Bs[rB * 18 + kB + 2] = make_float2(bv.z, bv.w);
        __syncthreads();
#pragma unroll
        for (int p = 0; p < 8; ++p) {
            ull b2[4];
#pragma unroll
            for (int c = 0; c < 4; ++c) b2[c] = Bsu[(tx + 16 * c) * 9 + p];
#pragma unroll
            for (int i = 0; i < 8; ++i) {
                ull a2 = Asu[(ty * 8 + i) * 10 + p];
                ffma2(acc2[i][0], a2, b2[0]);
                ffma2(acc2[i][1], a2, b2[1]);
                ffma2(acc2[i][2], a2, b2[2]);
                ffma2(acc2[i][3], a2, b2[3]);
            }
        }
    }

    float bias[4];
#pragma unroll
    for (int c = 0; c < 4; ++c) {
        int n = n0 + tx + 16 * c;
        bias[c] = b_ih[n] + b_hh[n];
    }
#pragma unroll
    for (int i = 0; i < 8; ++i) {
        float* dst = d_xg + (size_t)(m0 + ty * 8 + i) * GH + n0 + tx;
#pragma unroll
        for (int c = 0; c < 4; ++c)
            dst[16 * c] = hadd2(acc2[i][c]) + bias[c];
    }
}

// ---------------- kernel 2: persistent LSTM scan, full-k per CTA ------------------------
// CTA cc owns cols [4cc, 4cc+4) x 4 gates (16 rows) x 64 batches, full k=512.
// 2 k-teams of 128 threads (team tk covers k [256tk, 256tk+256) in 4 chunks of 64,
// cp.async double-buffered, per-chunk producer flags). Thread (lt&7 -> row pair,
// lt>>3 -> batch quad) accumulates 2x4 outputs. Teams reduce via smem; gate phase:
// thread (j=tid&3, b=tid>>2) owns one (col,b) output + its cell state in a register.
__global__ void __launch_bounds__(256, 1) scan_kernel(const float* __restrict__ W_hh) {
    extern __shared__ float sm[];
    float* sm_w  = sm + OFF_W;
    float* sm_ga = sm + OFF_GA;

    const int tid = threadIdx.x;
    const int cc  = blockIdx.x;
    const int tk  = tid >> 7;            // k-team
    const int lt  = tid & 127;
    const int rp  = lt & 7;              // row pair -> rows {2rp, 2rp+1}
    const int bq  = lt >> 3;             // batch quad -> batches {4bq..4bq+3}
    const int barid = 1 + tk;

    // gate-phase ownership
    const int gj = tid & 3;              // col-in-group
    const int gb = tid >> 2;             // batch
    const int gcol = 4 * cc + gj;

    // W slice -> smem once (rows r: gate q=r>>2, col j=r&3)
    for (int idx = tid; idx < NROWS * HH; idx += 256) {
        int r = idx >> 9, k = idx & 511;
        int grow = (r >> 2) * HH + 4 * cc + (r & 3);
        sm_w[r * WSROW + k] = W_hh[(size_t)grow * HH + k];
    }
    __syncthreads();

    float creg = 0.0f;                   // cell state for (gb, gcol)

    const ull* Ws2 = (const ull*)sm_w;   // row stride 257 ull
    const int kbase = tk * 256;
    const ull* wr0 = Ws2 + (2 * rp    ) * 257 + (kbase >> 1);
    const ull* wr1 = Ws2 + (2 * rp + 1) * 257 + (kbase >> 1);

    const uint32_t smem_h0 = (uint32_t)__cvta_generic_to_shared(sm + OFF_H);

    for (int t = 0; t < TT; ++t) {
        const float* hsrc = d_hbuf + (size_t)(t & 1) * HSLOT;

        // ---- chunk 0: wait producers, issue cp.async ----
        {
            int cc0 = tk * 64;                           // cols [256tk, +64) -> CTAs cc0..cc0+15
            if (lt < 16) {
                unsigned* f = &d_hflag[cc0 + lt].v;
                while (ld_acquire(f) < (unsigned)t) { }
            }
            team_bar(barid);
            const float* gsrc = hsrc + kbase;            // + chunk0 offset 0
            uint32_t sdst = smem_h0 + (tk * 2 + 0) * (HBUFSZ * 4);
#pragma unroll
            for (int i = 0; i < 8; ++i) {
                int idx = lt * 8 + i;                    // 0..1023
                int b = idx >> 4, seg = idx & 15;
                cp_async16(sdst + (b * HSROW + seg * 4) * 4,
                           gsrc + (size_t)b * HH + seg * 4);
            }
            cp_commit();
        }

        // ---- prefetch xg for our gate output (off the h critical path) ----
        float xr[4];
        {
            const float* xgp = d_xg + ((size_t)t * BB + gb) * GH;
#pragma unroll
            for (int q = 0; q < 4; ++q)
                xr[q] = __ldcs(xgp + q * HH + gcol);
        }

        // ---- accumulators ----
        ull acc[8];
#pragma unroll
        for (int i = 0; i < 8; ++i) acc[i] = 0ull;

        // ---- chunk loop: prefetch c+1, compute c ----
#pragma unroll
        for (int c = 0; c < NCHUNK; ++c) {
            if (c < NCHUNK - 1) {
                int cn = c + 1;
                int cc0 = tk * 64 + 16 * cn;
                if (lt < 16) {
                    unsigned* f = &d_hflag[cc0 + lt].v;
                    while (ld_acquire(f) < (unsigned)t) { }
                }
                team_bar(barid);
                const float* gsrc = hsrc + kbase + cn * KCHUNK;
                uint32_t sdst = smem_h0 + (tk * 2 + (cn & 1)) * (HBUFSZ * 4);
#pragma unroll
                for (int i = 0; i < 8; ++i) {
                    int idx = lt * 8 + i;
                    int b = idx >> 4, seg = idx & 15;
                    cp_async16(sdst + (b * HSROW + seg * 4) * 4,
                               gsrc + (size_t)b * HH + seg * 4);
                }
                cp_commit();
                cp_wait<1>();
            } else {
                cp_wait<0>();
            }
            team_bar(barid);

            const ull* hsu = (const ull*)(sm + OFF_H + (tk * 2 + (c & 1)) * HBUFSZ);
            const int co = c * 32;
#pragma unroll 8
            for (int k2 = 0; k2 < 32; ++k2) {
                ull w0 = wr0[co + k2];
                ull w1 = wr1[co + k2];
                const ull* hp = hsu + bq * (4 * (HSROW / 2)) + k2;
                ull h0 = hp[0], h1 = hp[HSROW / 2], h2 = hp[HSROW], h3 = hp[3 * (HSROW / 2)];
                ffma2(acc[0], w0, h0); ffma2(acc[1], w0, h1);
                ffma2(acc[2], w0, h2); ffma2(acc[3], w0, h3);
                ffma2(acc[4], w1, h0); ffma2(acc[5], w1, h1);
                ffma2(acc[6], w1, h2); ffma2(acc[7], w1, h3);
            }
        }

        // ---- stage team results, reduce across teams, gates ----
        {
            float* ga = sm_ga + tk * (NROWS * GAROW);
#pragma unroll
            for (int jj = 0; jj < 4; ++jj) {
                ga[(2 * rp    ) * GAROW + 4 * bq + jj] = hadd2(acc[    jj]);
                ga[(2 * rp + 1) * GAROW + 4 * bq + jj] = hadd2(acc[4 + jj]);
            }
        }
        __syncthreads();

        {
            const float* ga0 = sm_ga;
            const float* ga1 = sm_ga + NROWS * GAROW;
            float g[4];
#pragma unroll
            for (int q = 0; q < 4; ++q) {
                int r = q * 4 + gj;
                g[q] = ga0[r * GAROW + gb] + ga1[r * GAROW + gb] + xr[q];
            }
            float ig = sigfast(g[0]);
            float fg = sigfast(g[1]);
            float gg = tanhfast(g[2]);
            float og = sigfast(g[3]);
            creg = fg * creg + ig * gg;
            float* hdst = d_hbuf + (size_t)((t + 1) & 1) * HSLOT;
            __stcg(hdst + (size_t)gb * HH + gcol, og * tanhfast(creg));
        }
        __syncthreads();
        if (tid == 0) st_release(&d_hflag[cc].v, (unsigned)(t + 1));
    }
}

// ---------------- kernel 3: final FC (64x4x512) ----------------------------------------
__global__ void fc_kernel(const float* __restrict__ W_fc,
                          const float* __restrict__ b_fc,
                          float* __restrict__ out)
{
    const int b    = blockIdx.x;
    const int w    = threadIdx.x >> 5;   // class 0..3
    const int lane = threadIdx.x & 31;
    const float* hb = d_hbuf + (size_t)(TT & 1) * HSLOT + b * HH;  // h_512 in slot 0
    const float* wf = W_fc + w * HH;
    float s = 0.0f;
    for (int k = lane; k < HH; k += 32) s += hb[k] * wf[k];
#pragma unroll
    for (int o = 16; o; o >>= 1) s += __shfl_down_sync(0xffffffffu, s, o);
    if (lane == 0) out[b * CD + w] = s + b_fc[w];
}

// ---------------- host launcher ---------------------------------------------------------
extern "C" void kernel_launch(void* const* d_in, const int* in_sizes, int n_in,
                              void* d_out, int out_size) {
    const int*   x    = (const int*)  d_in[0];
    const float* emb  = (const float*)d_in[1];
    const float* W_ih = (const float*)d_in[2];
    const float* W_hh = (const float*)d_in[3];
    const float* b_ih = (const float*)d_in[4];
    const float* b_hh = (const float*)d_in[5];
    const float* W_fc = (const float*)d_in[6];
    const float* b_fc = (const float*)d_in[7];
    float* out = (float*)d_out;

    cudaFuncSetAttribute(scan_kernel, cudaFuncAttributeMaxDynamicSharedMemorySize, SMEM_SCAN);

    init_kernel<<<64, 256>>>();
    emb_gemm_kernel<<<dim3(GH / 64, (BB * TT) / 128), 256>>>(x, emb, W_ih, b_ih, b_hh);
    scan_kernel<<<NCC, 256, SMEM_SCAN>>>(W_hh);
    fc_kernel<<<BB, 128>>>(W_fc, b_fc, out);
}

// round 15
// speedup vs baseline: 1.1454x; 1.1454x over previous
#include <cuda_runtime.h>
#include <cstdint>

// ---------------- problem constants ----------------
#define BB   64      // batch
#define TT   512     // seq len
#define EE   256     // embed dim
#define HH   512     // hidden
#define GH   2048    // 4*H
#define CD   4       // classes

// ---------------- scan configuration ----------------
#define NCG  16                 // column groups (32 h-cols each, all 4 gates)
#define NKS  8                  // k splits (64 k each)
#define GRID_SCAN (NCG * NKS)   // 128 persistent CTAs, 1 per SM
#define KC   64                 // k per chunk
#define BH   32                 // batch half size
#define WROW 66                 // padded W smem row (floats) = 33 ull (odd -> conflict-free LDS.64)
#define HROW 68                 // padded h smem row (floats): 272B, 16B-aligned; h reads broadcast
#define SMEM_SCAN ((128 * WROW + BH * HROW) * 4)   // 42496 B dynamic smem

typedef unsigned long long ull;

#define PSLOT ((size_t)NCG * NKS * BB * 128)     // floats per partial slot
#define HSLOT ((size_t)BB * HH)                  // floats per h slot

// ---------------- device scratch (no allocs allowed) ----------------
struct alignas(256) PadFlag { unsigned v; unsigned pad[63]; };

__device__ float   d_xg[(size_t)TT * BB * GH];        // 256 MB: xg[(t*64+b)*2048 + g]
__device__ float   d_hbuf[2 * BB * HH];               // double-buffered h: slot t&1 holds h_t
__device__ float   d_part[2 * NCG * NKS * BB * 128];  // 8 MB: [slot][cg][src][b][row]
__device__ PadFlag d_hflag[NCG * NKS * 2];            // [(cg,ks)][half]: v=t+1 -> wrote h_{t+1}
__device__ PadFlag d_pflag[NCG * NKS * 2];            // [(cg,ks)][half]: v=t+1 -> partial of t out

// ---------------- helpers ----------------
__device__ __forceinline__ void ffma2(ull& d, ull a, ull b) {
    asm("fma.rn.f32x2 %0, %1, %2, %0;" : "+l"(d) : "l"(a), "l"(b));
}
__device__ __forceinline__ float hadd2(ull u) {
    float lo = __uint_as_float((unsigned)(u & 0xffffffffull));
    float hi = __uint_as_float((unsigned)(u >> 32));
    return lo + hi;
}
__device__ __forceinline__ float tanhfast(float x) {
    float r; asm("tanh.approx.f32 %0, %1;" : "=f"(r) : "f"(x)); return r;
}
__device__ __forceinline__ float sigfast(float x) {
    return fmaf(tanhfast(0.5f * x), 0.5f, 0.5f);
}
__device__ __forceinline__ void st_release(unsigned* p, unsigned v) {
    asm volatile("st.release.gpu.u32 [%0], %1;" :: "l"(p), "r"(v) : "memory");
}
__device__ __forceinline__ unsigned ld_acquire(unsigned* p) {
    unsigned v;
    asm volatile("ld.acquire.gpu.u32 %0, [%1];" : "=r"(v) : "l"(p) : "memory");
    return v;
}

// ---------------- kernel 0: per-launch reset ----------------
__global__ void init_kernel() {
    int i = blockIdx.x * blockDim.x + threadIdx.x;
    if (i < NCG * NKS * 2) { d_hflag[i].v = 0u; d_pflag[i].v = 0u; }
    for (int j = i; j < BB * HH; j += gridDim.x * blockDim.x) d_hbuf[j] = 0.0f;  // h_0 (slot 0)
}

// noop launch: shifts ncu's skip-window so the captured launch is scan_kernel
__global__ void noop_kernel() {}

// ---------------- kernel 1: fused embedding gather + input GEMM (FFMA2) ---------------
__global__ void __launch_bounds__(256) emb_gemm_kernel(
    const int*   __restrict__ x,
    const float* __restrict__ emb,
    const float* __restrict__ W_ih,
    const float* __restrict__ b_ih,
    const float* __restrict__ b_hh)
{
    __shared__ float As[128 * 20];
    __shared__ float Bs[64 * 18];
    const int tid = threadIdx.x;
    const int m0  = blockIdx.y * 128;
    const int n0  = blockIdx.x * 64;

    const int rA = tid >> 1, kA = (tid & 1) * 8;
    const int tpos = (m0 + rA) >> 6, bpos = rA & 63;
    const float* aptr = emb + (size_t)x[bpos * TT + tpos] * EE + kA;
    const int rB = tid >> 2, kB = (tid & 3) * 4;
    const float* bptr = W_ih + (size_t)(n0 + rB) * EE + kB;

    const int tx = tid & 15, ty = tid >> 4;

    ull acc2[8][4];
#pragma unroll
    for (int i = 0; i < 8; ++i)
#pragma unroll
        for (int c = 0; c < 4; ++c) acc2[i][c] = 0ull;

    const ull* Asu = (const ull*)As;           // row stride 10 ull
    const ull* Bsu = (const ull*)Bs;           // row stride 9 ull

    for (int kt = 0; kt < EE; kt += 16) {
        float4 a0 = *(const float4*)(aptr + kt);
        float4 a1 = *(const float4*)(aptr + kt + 4);
        float4 bv = *(const float4*)(bptr + kt);
        __syncthreads();
        *(float4*)&As[rA * 20 + kA]     = a0;
        *(float4*)&As[rA * 20 + kA + 4] = a1;
        *(float2*)&Bs[rB * 18 + kB]     = make_float2(bv.x, bv.y);
        *(float2*)&Bs[rB * 18 + kB + 2] = make_float2(bv.z, bv.w);
        __syncthreads();
#pragma unroll
        for (int p = 0; p < 8; ++p) {
            ull b2[4];
#pragma unroll
            for (int c = 0; c < 4; ++c) b2[c] = Bsu[(tx + 16 * c) * 9 + p];
#pragma unroll
            for (int i = 0; i < 8; ++i) {
                ull a2 = Asu[(ty * 8 + i) * 10 + p];
                ffma2(acc2[i][0], a2, b2[0]);
                ffma2(acc2[i][1], a2, b2[1]);
                ffma2(acc2[i][2], a2, b2[2]);
                ffma2(acc2[i][3], a2, b2[3]);
            }
        }
    }

    float bias[4];
#pragma unroll
    for (int c = 0; c < 4; ++c) {
        int n = n0 + tx + 16 * c;
        bias[c] = b_ih[n] + b_hh[n];
    }
#pragma unroll
    for (int i = 0; i < 8; ++i) {
        float* dst = d_xg + (size_t)(m0 + ty * 8 + i) * GH + n0 + tx;
#pragma unroll
        for (int c = 0; c < 4; ++c)
            dst[16 * c] = hadd2(acc2[i][c]) + bias[c];
    }
}

// ---------------- kernel 2: persistent LSTM scan, batch-halved pipeline ----------------
// CTA (cg = bid&15, ks = bid>>4). Per step, per batch-half X in {0,1}:
//   P_X: wait 16 h-flags(X,t) -> stage h (32b x 64k) -> GEMV (thread rg=tid&31 row,
//        bg=tid>>5 -> 4 batches; acc[4][4]) -> publish partials -> release pflag(X).
//   R_X: wait 8 p-flags(X) -> (tid<128: bj=tid>>5, c=tid&31) reduce 8 slabs for
//        (b = 32X+4ks+bj, col = 32cg+c), gates, cell state in reg, write h_{t+1},
//        release hflag(X).
// Order P_A P_B R_A R_B hides every flag-wake behind the other half's compute.
__global__ void __launch_bounds__(256, 1) scan_kernel(const float* __restrict__ W_hh) {
    extern __shared__ float sm[];
    float* sm_w = sm;                    // [128][WROW]
    float* sm_h = sm + 128 * WROW;       // [32][HROW]

    const int tid = threadIdx.x;
    const int cg  = blockIdx.x & (NCG - 1);
    const int ks  = blockIdx.x >> 4;
    const int rg  = tid & 31;
    const int bg  = tid >> 5;            // GEMV: batch quad within half
    const int bj  = tid >> 5;            // reduce: batch-in-quad (tid<128 -> 0..3)
    const int c   = tid & 31;            // reduce: col-in-group
    const int colred = cg * 32 + c;

    // W_hh slice -> smem once; reused for all 512 steps.
    for (int idx = tid; idx < 128 * KC; idx += 256) {
        int r = idx >> 6, k = idx & 63;
        int grow = (r >> 5) * HH + cg * 32 + (r & 31);
        sm_w[r * WROW + k] = W_hh[(size_t)grow * HH + ks * KC + k];
    }

    float creg[2] = {0.0f, 0.0f};        // cell state for (32X+4ks+bj, colred)
    float xr2[2][4];                     // xg prefetch per half

    const ull* Ws2 = (const ull*)sm_w;   // row stride 33 ull (odd -> conflict-free)
    const ull* Hs2 = (const ull*)sm_h;   // row stride 34 ull (h reads are broadcast)

    for (int t = 0; t < TT; ++t) {
        const int slot = t & 1;

        // ================= produce phases =================
#pragma unroll
        for (int X = 0; X < 2; ++X) {
            // wait the 16 producers of this half's h_t chunk
            if (tid < 16) {
                int cgp = 2 * ks + (tid >> 3);
                int src = tid & 7;
                unsigned* f = &d_hflag[((cgp * NKS + src) << 1) + X].v;
                while (ld_acquire(f) < (unsigned)t) { }
            }
            __syncthreads();             // also covers W load at t==0 / GEMV of prev half

            // stage h chunk: 32 batches x 64 k (512 float4, 2 per thread)
            const float* hsrc = d_hbuf + (size_t)slot * HSLOT + (size_t)(X * BH) * HH + ks * KC;
#pragma unroll
            for (int v = 0; v < 2; ++v) {
                int idx = v * 256 + tid;             // 0..511
                int b = idx >> 4, seg = idx & 15;
                float4 hv = __ldcg((const float4*)(hsrc + (size_t)b * HH + seg * 4));
                *(float4*)(sm_h + b * HROW + seg * 4) = hv;
            }
            // xg prefetch for this half's reduce outputs (off critical path)
            if (tid < 128) {
                int bred = X * BH + ks * 4 + bj;
                const float* xgp = d_xg + ((size_t)t * BB + bred) * GH;
#pragma unroll
                for (int q = 0; q < 4; ++q)
                    xr2[X][q] = __ldcs(xgp + q * HH + colred);
            }
            __syncthreads();

            // GEMV: acc[q][j] = pairwise-k  W[q*32+rg] . h[4bg+j]
            ull acc[4][4];
#pragma unroll
            for (int q = 0; q < 4; ++q)
#pragma unroll
                for (int j = 0; j < 4; ++j) acc[q][j] = 0ull;

#pragma unroll 8
            for (int k2 = 0; k2 < 32; ++k2) {
                ull w0 = Ws2[(rg     ) * 33 + k2];
                ull w1 = Ws2[(rg + 32) * 33 + k2];
                ull w2 = Ws2[(rg + 64) * 33 + k2];
                ull w3 = Ws2[(rg + 96) * 33 + k2];
                const ull* hp = Hs2 + (4 * bg) * 34 + k2;
#pragma unroll
                for (int j = 0; j < 4; ++j) {
                    ull hv = hp[j * 34];
                    ffma2(acc[0][j], w0, hv);
                    ffma2(acc[1][j], w1, hv);
                    ffma2(acc[2][j], w2, hv);
                    ffma2(acc[3][j], w3, hv);
                }
            }

            // publish partials: [cg][src=ks][b_abs][row], coalesced over rg
            {
                float* pb = d_part + (size_t)slot * PSLOT + (size_t)((cg * NKS + ks) * BB) * 128;
#pragma unroll
                for (int j = 0; j < 4; ++j) {
                    float* row = pb + (size_t)(X * BH + 4 * bg + j) * 128 + rg;
                    __stcg(row     , hadd2(acc[0][j]));
                    __stcg(row + 32, hadd2(acc[1][j]));
                    __stcg(row + 64, hadd2(acc[2][j]));
                    __stcg(row + 96, hadd2(acc[3][j]));
                }
            }
            __syncthreads();
            if (tid == 0) st_release(&d_pflag[((cg * NKS + ks) << 1) + X].v, (unsigned)(t + 1));
        }

        // ================= reduce phases =================
#pragma unroll
        for (int X = 0; X < 2; ++X) {
            if (tid < 8) {
                unsigned* f = &d_pflag[((cg * NKS + tid) << 1) + X].v;
                while (ld_acquire(f) < (unsigned)(t + 1)) { }
            }
            __syncthreads();

            if (tid < 128) {
                const int bred = X * BH + ks * 4 + bj;
                float g0 = xr2[X][0], g1 = xr2[X][1], g2 = xr2[X][2], g3 = xr2[X][3];
                const float* ps = d_part + (size_t)slot * PSLOT;
#pragma unroll
                for (int src = 0; src < NKS; ++src) {
                    const float* row = ps + (size_t)((cg * NKS + src) * BB + bred) * 128 + c;
                    g0 += __ldcg(row);
                    g1 += __ldcg(row + 32);
                    g2 += __ldcg(row + 64);
                    g3 += __ldcg(row + 96);
                }
                float ig = sigfast(g0);
                float fg = sigfast(g1);
                float gg = tanhfast(g2);
                float og = sigfast(g3);
                creg[X] = fg * creg[X] + ig * gg;
                float* hdst = d_hbuf + (size_t)((t + 1) & 1) * HSLOT;
                __stcg(hdst + (size_t)bred * HH + colred, og * tanhfast(creg[X]));
            }
            __syncthreads();
            if (tid == 0) st_release(&d_hflag[((cg * NKS + ks) << 1) + X].v, (unsigned)(t + 1));
        }
    }
}

// ---------------- kernel 3: final FC (64x4x512) ----------------------------------------
__global__ void fc_kernel(const float* __restrict__ W_fc,
                          const float* __restrict__ b_fc,
                          float* __restrict__ out)
{
    const int b    = blockIdx.x;
    const int w    = threadIdx.x >> 5;   // class 0..3
    const int lane = threadIdx.x & 31;
    const float* hb = d_hbuf + (size_t)(TT & 1) * HSLOT + b * HH;  // h_512 in slot 0
    const float* wf = W_fc + w * HH;
    float s = 0.0f;
    for (int k = lane; k < HH; k += 32) s += hb[k] * wf[k];
#pragma unroll
    for (int o = 16; o; o >>= 1) s += __shfl_down_sync(0xffffffffu, s, o);
    if (lane == 0) out[b * CD + w] = s + b_fc[w];
}

// ---------------- host launcher ---------------------------------------------------------
extern "C" void kernel_launch(void* const* d_in, const int* in_sizes, int n_in,
                              void* d_out, int out_size) {
    const int*   x    = (const int*)  d_in[0];
    const float* emb  = (const float*)d_in[1];
    const float* W_ih = (const float*)d_in[2];
    const float* W_hh = (const float*)d_in[3];
    const float* b_ih = (const float*)d_in[4];
    const float* b_hh = (const float*)d_in[5];
    const float* W_fc = (const float*)d_in[6];
    const float* b_fc = (const float*)d_in[7];
    float* out = (float*)d_out;

    cudaFuncSetAttribute(scan_kernel, cudaFuncAttributeMaxDynamicSharedMemorySize, SMEM_SCAN);

    init_kernel<<<64, 256>>>();
    noop_kernel<<<1, 32>>>();   // shifts ncu capture window onto scan_kernel
    emb_gemm_kernel<<<dim3(GH / 64, (BB * TT) / 128), 256>>>(x, emb, W_ih, b_ih, b_hh);
    scan_kernel<<<GRID_SCAN, 256, SMEM_SCAN>>>(W_hh);
    fc_kernel<<<BB, 128>>>(W_fc, b_fc, out);
}

// round 16
// speedup vs baseline: 1.3494x; 1.1782x over previous
#include <cuda_runtime.h>
#include <cstdint>

// ---------------- problem constants ----------------
#define BB   64      // batch
#define TT   512     // seq len
#define EE   256     // embed dim
#define HH   512     // hidden
#define GH   2048    // 4*H
#define CD   4       // classes

// ---------------- scan configuration ----------------
#define NCG  16                 // column groups (32 h-cols each, all 4 gates)
#define NKS  8                  // k splits (64 k each)
#define GRID_SCAN (NCG * NKS)   // 128 persistent CTAs, 1 per SM
#define KC   64                 // k per chunk
#define WROW 66                 // padded W smem row (floats) = 33 ull (odd -> conflict-free LDS.64)
#define SMEM_SCAN ((128 * WROW + BB * KC) * 4)   // 50176 B dynamic smem

typedef unsigned long long ull;

#define PSLOT ((size_t)NCG * NKS * BB * 128)     // floats per partial slot
#define HSLOT ((size_t)BB * HH)                  // floats per h slot

// ---------------- device scratch (no allocs allowed) ----------------
struct alignas(256) PadFlag { unsigned v; unsigned pad[63]; };

__device__ float   d_xg[(size_t)TT * BB * GH];        // 256 MB: xg[(t*64+b)*2048 + g]
__device__ float   d_hbuf[2 * BB * HH];               // double-buffered h: slot t&1 holds h_t
__device__ float   d_part[2 * NCG * NKS * BB * 128];  // 8 MB: [slot][cg][src][b][row]
__device__ PadFlag d_hflag[NCG * NKS];                // v=t+1: (cg,ks) wrote its h_{t+1} batches
__device__ PadFlag d_pflag[NCG * NKS];                // v=t+1: (cg,ks) published step-t partial

// ---------------- helpers ----------------
__device__ __forceinline__ void ffma2(ull& d, ull a, ull b) {
    asm("fma.rn.f32x2 %0, %1, %2, %0;" : "+l"(d) : "l"(a), "l"(b));
}
__device__ __forceinline__ float hadd2(ull u) {
    float lo = __uint_as_float((unsigned)(u & 0xffffffffull));
    float hi = __uint_as_float((unsigned)(u >> 32));
    return lo + hi;
}
__device__ __forceinline__ float tanhfast(float x) {
    float r; asm("tanh.approx.f32 %0, %1;" : "=f"(r) : "f"(x)); return r;
}
__device__ __forceinline__ float sigfast(float x) {
    return fmaf(tanhfast(0.5f * x), 0.5f, 0.5f);
}
__device__ __forceinline__ void st_release(unsigned* p, unsigned v) {
    asm volatile("st.release.gpu.u32 [%0], %1;" :: "l"(p), "r"(v) : "memory");
}
__device__ __forceinline__ unsigned ld_acquire(unsigned* p) {
    unsigned v;
    asm volatile("ld.acquire.gpu.u32 %0, [%1];" : "=r"(v) : "l"(p) : "memory");
    return v;
}

// ---------------- kernel 0: per-launch reset ----------------
__global__ void init_kernel() {
    int i = blockIdx.x * blockDim.x + threadIdx.x;
    if (i < NCG * NKS) { d_hflag[i].v = 0u; d_pflag[i].v = 0u; }
    for (int j = i; j < BB * HH; j += gridDim.x * blockDim.x) d_hbuf[j] = 0.0f;  // h_0 (slot 0)
}

// noop launch: keeps ncu's skip-window aligned on scan_kernel
__global__ void noop_kernel() {}

// ---------------- kernel 1: fused embedding gather + input GEMM (FFMA2) ---------------
__global__ void __launch_bounds__(256) emb_gemm_kernel(
    const int*   __restrict__ x,
    const float* __restrict__ emb,
    const float* __restrict__ W_ih,
    const float* __restrict__ b_ih,
    const float* __restrict__ b_hh)
{
    __shared__ float As[128 * 20];
    __shared__ float Bs[64 * 18];
    const int tid = threadIdx.x;
    const int m0  = blockIdx.y * 128;
    const int n0  = blockIdx.x * 64;

    const int rA = tid >> 1, kA = (tid & 1) * 8;
    const int tpos = (m0 + rA) >> 6, bpos = rA & 63;
    const float* aptr = emb + (size_t)x[bpos * TT + tpos] * EE + kA;
    const int rB = tid >> 2, kB = (tid & 3) * 4;
    const float* bptr = W_ih + (size_t)(n0 + rB) * EE + kB;

    const int tx = tid & 15, ty = tid >> 4;

    ull acc2[8][4];
#pragma unroll
    for (int i = 0; i < 8; ++i)
#pragma unroll
        for (int c = 0; c < 4; ++c) acc2[i][c] = 0ull;

    const ull* Asu = (const ull*)As;           // row stride 10 ull
    const ull* Bsu = (const ull*)Bs;           // row stride 9 ull

    for (int kt = 0; kt < EE; kt += 16) {
        float4 a0 = *(const float4*)(aptr + kt);
        float4 a1 = *(const float4*)(aptr + kt + 4);
        float4 bv = *(const float4*)(bptr + kt);
        __syncthreads();
        *(float4*)&As[rA * 20 + kA]     = a0;
        *(float4*)&As[rA * 20 + kA + 4] = a1;
        *(float2*)&Bs[rB * 18 + kB]     = make_float2(bv.x, bv.y);
        *(float2*)&Bs[rB * 18 + kB + 2] = make_float2(bv.z, bv.w);
        __syncthreads();
#pragma unroll
        for (int p = 0; p < 8; ++p) {
            ull b2[4];
#pragma unroll
            for (int c = 0; c < 4; ++c) b2[c] = Bsu[(tx + 16 * c) * 9 + p];
#pragma unroll
            for (int i = 0; i < 8; ++i) {
                ull a2 = Asu[(ty * 8 + i) * 10 + p];
                ffma2(acc2[i][0], a2, b2[0]);
                ffma2(acc2[i][1], a2, b2[1]);
                ffma2(acc2[i][2], a2, b2[2]);
                ffma2(acc2[i][3], a2, b2[3]);
            }
        }
    }

    float bias[4];
#pragma unroll
    for (int c = 0; c < 4; ++c) {
        int n = n0 + tx + 16 * c;
        bias[c] = b_ih[n] + b_hh[n];
    }
#pragma unroll
    for (int i = 0; i < 8; ++i) {
        float* dst = d_xg + (size_t)(m0 + ty * 8 + i) * GH + n0 + tx;
#pragma unroll
        for (int c = 0; c < 4; ++c)
            dst[16 * c] = hadd2(acc2[i][c]) + bias[c];
    }
}

// ---------------- kernel 2: persistent LSTM scan, 512 threads --------------------------
// CTA (cg = bid&15, ks = bid>>4): cg owns h-cols [cg*32,+32) x 4 gates, ks owns
// k in [ks*64,+64).
// GEMV: warp wid=(bg<<1)|qh; thread covers gate-rows {(2qh+i)*32+lane : i<2} and
//   batches [8bg, 8bg+8) -> acc[2][8]; per k-pair 2 W + 8 broadcast h LDS.64.
// Reduce: lane-pair per output; thread (o=tid>>1, half=tid&1) sums slabs
//   [4*half, 4*half+4) for (b=8ks+(o>>5), col=32cg+(o&31)), shfl_xor combine;
//   even lane holds cell state + writes h.
__global__ void __launch_bounds__(512, 1) scan_kernel(const float* __restrict__ W_hh) {
    extern __shared__ float sm[];
    float* sm_w = sm;                    // [128][WROW]
    float* sm_h = sm + 128 * WROW;       // [64][64]

    const int tid  = threadIdx.x;
    const int cg   = blockIdx.x & (NCG - 1);
    const int ks   = blockIdx.x >> 4;
    const int lane = tid & 31;
    const int wid  = tid >> 5;           // 0..15
    const int qh   = wid & 1;            // gate-row half
    const int bg   = wid >> 1;           // batch octet
    const int b0   = bg * 8;
    // reduce decomposition
    const int half = tid & 1;
    const int o    = tid >> 1;           // 0..255
    const int bred = ks * 8 + (o >> 5);
    const int colred = cg * 32 + (o & 31);

    // W_hh slice -> smem once; reused for all 512 steps.
    for (int idx = tid; idx < 128 * KC; idx += 512) {
        int r = idx >> 6, k = idx & 63;
        int grow = (r >> 5) * HH + cg * 32 + (r & 31);
        sm_w[r * WROW + k] = W_hh[(size_t)grow * HH + ks * KC + k];
    }

    float creg = 0.0f;                   // cell state for (bred, colred), even lanes only

    const ull* Ws2 = (const ull*)sm_w;   // row stride 33 ull (odd -> conflict-free)
    const ull* Hs2 = (const ull*)sm_h;   // row stride 32 ull (broadcast reads)
    const ull* wr0 = Ws2 + (qh * 64 + lane) * 33;
    const ull* wr1 = Ws2 + (qh * 64 + 32 + lane) * 33;

    for (int t = 0; t < TT; ++t) {
        const int slot = t & 1;

        // --- wait for the 16 producers of our h_t chunk ---
        if (tid < 16) {
            int cgp = 2 * ks + (tid >> 3);
            int src = tid & 7;
            unsigned* f = &d_hflag[cgp * NKS + src].v;
            while (ld_acquire(f) < (unsigned)t) { }
        }
        __syncthreads();                 // also covers one-time W load at t==0

        // --- stage h_t chunk: 1024 float4, 2 per thread (L2-coherent) ---
        const float* hsrc = d_hbuf + (size_t)slot * HSLOT + ks * KC;
#pragma unroll
        for (int v = 0; v < 2; ++v) {
            int idx = v * 512 + tid;                 // 0..1023
            int b = idx >> 4, seg = idx & 15;
            float4 hv = __ldcg((const float4*)(hsrc + (size_t)b * HH + seg * 4));
            *(float4*)(sm_h + b * KC + seg * 4) = hv;
        }

        // --- prefetch xg for our reduce output (even lanes; off the h critical path) ---
        float xr[4];
        if (half == 0) {
            const float* xgp = d_xg + ((size_t)t * BB + bred) * GH;
#pragma unroll
            for (int q = 0; q < 4; ++q)
                xr[q] = __ldcs(xgp + q * HH + colred);
        }
        __syncthreads();

        // --- partial GEMV ---
        ull acc[2][8];
#pragma unroll
        for (int i = 0; i < 2; ++i)
#pragma unroll
            for (int j = 0; j < 8; ++j) acc[i][j] = 0ull;

#pragma unroll 8
        for (int k2 = 0; k2 < 32; ++k2) {
            ull w0 = wr0[k2];
            ull w1 = wr1[k2];
            const ull* hp = Hs2 + b0 * 32 + k2;
#pragma unroll
            for (int j = 0; j < 8; ++j) {
                ull hv = hp[j * 32];
                ffma2(acc[0][j], w0, hv);
                ffma2(acc[1][j], w1, hv);
            }
        }

        // --- publish partials: [cg][src=ks][b][row], coalesced over lane ---
        {
            float* pb = d_part + (size_t)slot * PSLOT + (size_t)((cg * NKS + ks) * BB) * 128;
#pragma unroll
            for (int j = 0; j < 8; ++j) {
                float* row = pb + (size_t)(b0 + j) * 128 + qh * 64 + lane;
                __stcg(row,      hadd2(acc[0][j]));
                __stcg(row + 32, hadd2(acc[1][j]));
            }
        }
        __syncthreads();
        if (tid == 0) st_release(&d_pflag[cg * NKS + ks].v, (unsigned)(t + 1));

        // --- wait for all 8 k-slices of our cg ---
        if (tid < 8) {
            unsigned* f = &d_pflag[cg * NKS + tid].v;
            while (ld_acquire(f) < (unsigned)(t + 1)) { }
        }
        __syncthreads();

        // --- reduce: each lane sums 4 slabs for (bred, colred); pair-combine via shfl ---
        float g0 = 0.f, g1 = 0.f, g2 = 0.f, g3 = 0.f;
        {
            const float* ps = d_part + (size_t)slot * PSLOT;
#pragma unroll
            for (int s = 0; s < 4; ++s) {
                int src = half * 4 + s;
                const float* row = ps + (size_t)((cg * NKS + src) * BB + bred) * 128 + (o & 31);
                g0 += __ldcg(row);
                g1 += __ldcg(row + 32);
                g2 += __ldcg(row + 64);
                g3 += __ldcg(row + 96);
            }
        }
        g0 += __shfl_xor_sync(0xffffffffu, g0, 1);
        g1 += __shfl_xor_sync(0xffffffffu, g1, 1);
        g2 += __shfl_xor_sync(0xffffffffu, g2, 1);
        g3 += __shfl_xor_sync(0xffffffffu, g3, 1);

        if (half == 0) {
            g0 += xr[0]; g1 += xr[1]; g2 += xr[2]; g3 += xr[3];
            float ig = sigfast(g0);
            float fg = sigfast(g1);
            float gg = tanhfast(g2);
            float og = sigfast(g3);
            creg = fg * creg + ig * gg;
            float* hdst = d_hbuf + (size_t)((t + 1) & 1) * HSLOT;
            __stcg(hdst + (size_t)bred * HH + colred, og * tanhfast(creg));
        }
        __syncthreads();
        if (tid == 0) st_release(&d_hflag[cg * NKS + ks].v, (unsigned)(t + 1));
    }
}

// ---------------- kernel 3: final FC (64x4x512) ----------------------------------------
__global__ void fc_kernel(const float* __restrict__ W_fc,
                          const float* __restrict__ b_fc,
                          float* __restrict__ out)
{
    const int b    = blockIdx.x;
    const int w    = threadIdx.x >> 5;   // class 0..3
    const int lane = threadIdx.x & 31;
    const float* hb = d_hbuf + (size_t)(TT & 1) * HSLOT + b * HH;  // h_512 in slot 0
    const float* wf = W_fc + w * HH;
    float s = 0.0f;
    for (int k = lane; k < HH; k += 32) s += hb[k] * wf[k];
#pragma unroll
    for (int oo = 16; oo; oo >>= 1) s += __shfl_down_sync(0xffffffffu, s, oo);
    if (lane == 0) out[b * CD + w] = s + b_fc[w];
}

// ---------------- host launcher ---------------------------------------------------------
extern "C" void kernel_launch(void* const* d_in, const int* in_sizes, int n_in,
                              void* d_out, int out_size) {
    const int*   x    = (const int*)  d_in[0];
    const float* emb  = (const float*)d_in[1];
    const float* W_ih = (const float*)d_in[2];
    const float* W_hh = (const float*)d_in[3];
    const float* b_ih = (const float*)d_in[4];
    const float* b_hh = (const float*)d_in[5];
    const float* W_fc = (const float*)d_in[6];
    const float* b_fc = (const float*)d_in[7];
    float* out = (float*)d_out;

    cudaFuncSetAttribute(scan_kernel, cudaFuncAttributeMaxDynamicSharedMemorySize, SMEM_SCAN);

    init_kernel<<<64, 256>>>();
    noop_kernel<<<1, 32>>>();   // keeps ncu capture window on scan_kernel
    emb_gemm_kernel<<<dim3(GH / 64, (BB * TT) / 128), 256>>>(x, emb, W_ih, b_ih, b_hh);
    scan_kernel<<<GRID_SCAN, 512, SMEM_SCAN>>>(W_hh);
    fc_kernel<<<BB, 128>>>(W_fc, b_fc, out);
}